// round 6
// baseline (speedup 1.0000x reference)
#include <cuda_runtime.h>

#define BB   8192
#define NW   4
#define LL   16
#define EE   128
#define HH   128
#define VV   64
#define BN_TOT (BB*NW)
#define G4H  512

typedef unsigned long long u64;

__device__ __align__(16) float g_G[VV * G4H];          // input gates per vocab word
__device__ __align__(16) float g_Wt[HH * G4H];         // W_hh transposed: [k][j]
__device__ __align__(16) float g_reps[(size_t)BN_TOT * HH];
__device__ int g_perm[BN_TOT];
__device__ int g_cursor[16];

__device__ __forceinline__ u64 dup2(float a) {
    u64 v; asm("mov.b64 %0, {%1, %1};" : "=l"(v) : "f"(a)); return v;
}
__device__ __forceinline__ u64 pk(float a, float b) {
    u64 v; asm("mov.b64 %0, {%1, %2};" : "=l"(v) : "f"(a), "f"(b)); return v;
}
__device__ __forceinline__ void unpk(u64 v, float& a, float& b) {
    asm("mov.b64 {%0, %1}, %2;" : "=f"(a), "=f"(b) : "l"(v));
}
__device__ __forceinline__ float tanha(float x) {
    float y; asm("tanh.approx.f32 %0, %1;" : "=f"(y) : "f"(x)); return y;
}
__device__ __forceinline__ float sigma_(float x) {        // sigmoid via tanh
    return fmaf(0.5f, tanha(0.5f * x), 0.5f);
}
__device__ __forceinline__ float sigm_exact(float x) {
    return __fdividef(1.f, 1.f + __expf(-x));
}

// ---- one-block: histogram lengths (desc bins) + exclusive scan -> g_cursor ----
__global__ void k_prep(const int* __restrict__ lengths) {
    __shared__ int bins[16][33];
    int tid = threadIdx.x, w = tid >> 5;
    for (int i = tid; i < 16 * 33; i += 1024) (&bins[0][0])[i] = 0;
    __syncthreads();
    for (int i = tid; i < BN_TOT; i += 1024)
        atomicAdd(&bins[16 - lengths[i]][w], 1);
    __syncthreads();
    if (tid < 16) {
        int s = 0;
        for (int ww = 0; ww < 32; ++ww) s += bins[tid][ww];
        bins[tid][32] = s;
    }
    __syncthreads();
    if (tid == 0) {
        int cum = 0;
        for (int b = 0; b < 16; ++b) { g_cursor[b] = cum; cum += bins[b][32]; }
    }
}

// ---- scatter rows into length-descending order ----
__global__ void k_scatter(const int* __restrict__ lengths) {
    __shared__ int cnt[16], base[16];
    int tid = threadIdx.x;
    if (tid < 16) cnt[tid] = 0;
    __syncthreads();
    int bn  = blockIdx.x * 256 + tid;
    int bin = 16 - lengths[bn];
    int rank = atomicAdd(&cnt[bin], 1);
    __syncthreads();
    if (tid < 16) base[tid] = atomicAdd(&g_cursor[tid], cnt[tid]);
    __syncthreads();
    g_perm[base[bin] + rank] = bn;
}

// ---- blocks 0..63: G[v][j] = emb[v].W_ih[j] + b_ih[j] + b_hh[j]
// ---- blocks 64..95: transpose W_hh -> g_Wt[k][j]
__global__ void k_gates(const float* __restrict__ emb, const float* __restrict__ Wih,
                        const float* __restrict__ bih, const float* __restrict__ bhh,
                        const float* __restrict__ Whh) {
    int j = threadIdx.x;
    if (blockIdx.x < 64) {
        int v = blockIdx.x;
        const float* e = emb + v * EE;
        const float* w = Wih + j * EE;
        float s = bih[j] + bhh[j];
#pragma unroll 8
        for (int k = 0; k < EE; ++k) s = fmaf(e[k], w[k], s);
        g_G[v * G4H + j] = s;
    } else {
        int kb = (blockIdx.x - 64) * 4;
#pragma unroll
        for (int kk = 0; kk < 4; ++kk)
            g_Wt[(kb + kk) * G4H + j] = Whh[j * HH + kb + kk];
    }
}

// ---- masked LSTM over length-sorted rows ----
// CTA = 32 rows, 256 threads. Warp (rh,ch): rh owns rows [8rh,8rh+8), ch a
// 64-wide hidden half; thread cols {g*128 + 64*ch + 2*lane, +1}. W fetched via
// coalesced LDG.64 from transposed g_Wt (L1-resident, warp-staggered k order).
// Only the 2 warps sharing a row group synchronize (named barrier), and each
// group runs to its own max length.
__global__ __launch_bounds__(256, 2)
void k_lstm(const int* __restrict__ word_ids, const int* __restrict__ lengths) {
    __shared__ __align__(16) float sH[32][128];
    __shared__ int sBn[32], sLen[32], sWid[32][LL];

    int tid  = threadIdx.x;
    int lane = tid & 31;
    int wrp  = tid >> 5;
    int rh   = wrp >> 1;
    int ch   = wrp & 1;
    int base = blockIdx.x * 32;
    int colh = 64 * ch + 2 * lane;
    int row0 = rh * 8;

    if (tid < 32) {
        int bn = g_perm[base + tid];
        sBn[tid] = bn; sLen[tid] = lengths[bn];
    }
    __syncthreads();
    for (int i = tid; i < 32 * LL; i += 256) {
        int r = i >> 4, t = i & 15;
        sWid[r][t] = word_ids[sBn[r] * LL + t];
    }
    for (int i = tid; i < 32 * 128; i += 256) (&sH[0][0])[i] = 0.f;
    __syncthreads();

    int tLen = 0;
#pragma unroll
    for (int r = 0; r < 8; ++r) tLen = max(tLen, sLen[row0 + r]);

    // warp-staggered k start: 16 warps/SM spread over 64 k-pair slots
    int sstart = ((wrp + ((blockIdx.x & 1) << 3)) & 15) << 2;

    float c[8][2];
#pragma unroll
    for (int r = 0; r < 8; ++r) { c[r][0] = 0.f; c[r][1] = 0.f; }

    for (int t = 0; t < tLen; ++t) {
        u64 acc[8][4];
#pragma unroll
        for (int r = 0; r < 8; ++r) {
            const u64* Gp = (const u64*)(g_G + sWid[row0 + r][t] * G4H + colh);
#pragma unroll
            for (int g = 0; g < 4; ++g) acc[r][g] = Gp[g * 64];
        }
        for (int kc = 0; kc < 64; ++kc) {
            int k = (((kc + sstart) & 63) << 1);
            float2 h2[8];
#pragma unroll
            for (int r = 0; r < 8; ++r)
                h2[r] = *(const float2*)&sH[row0 + r][k];
            u64 wA[4], wB[4];
            const float* wk = g_Wt + k * G4H + colh;
#pragma unroll
            for (int g = 0; g < 4; ++g) wA[g] = *(const u64*)(wk + g * 128);
#pragma unroll
            for (int g = 0; g < 4; ++g) wB[g] = *(const u64*)(wk + G4H + g * 128);
#pragma unroll
            for (int r = 0; r < 8; ++r) {
                u64 ha = dup2(h2[r].x);
#pragma unroll
                for (int g = 0; g < 4; ++g)
                    asm("fma.rn.f32x2 %0, %1, %2, %0;"
                        : "+l"(acc[r][g]) : "l"(ha), "l"(wA[g]));
            }
#pragma unroll
            for (int r = 0; r < 8; ++r) {
                u64 hb = dup2(h2[r].y);
#pragma unroll
                for (int g = 0; g < 4; ++g)
                    asm("fma.rn.f32x2 %0, %1, %2, %0;"
                        : "+l"(acc[r][g]) : "l"(hb), "l"(wB[g]));
            }
        }
        // pair barrier: h reads of this step complete (warps 2rh, 2rh+1)
        asm volatile("bar.sync %0, 64;" :: "r"(rh + 1) : "memory");
#pragma unroll
        for (int r = 0; r < 8; ++r) {
            int row = row0 + r;
            if (t < sLen[row]) {
                float i0, i1, f0, f1, gg0, gg1, o0, o1;
                unpk(acc[r][0], i0, i1); unpk(acc[r][1], f0, f1);
                unpk(acc[r][2], gg0, gg1); unpk(acc[r][3], o0, o1);
                float c0 = fmaf(sigma_(f0), c[r][0], sigma_(i0) * tanha(gg0));
                float c1 = fmaf(sigma_(f1), c[r][1], sigma_(i1) * tanha(gg1));
                c[r][0] = c0; c[r][1] = c1;
                *(u64*)(&sH[row][colh]) = pk(sigma_(o0) * tanha(c0),
                                             sigma_(o1) * tanha(c1));
            }
        }
        // pair barrier: h writes visible before next step's reads
        asm volatile("bar.sync %0, 64;" :: "r"(rh + 1) : "memory");
    }
#pragma unroll
    for (int r = 0; r < 8; ++r) {
        size_t bn = (size_t)sBn[row0 + r];
        *(u64*)(g_reps + bn * HH + colh) = pk(c[r][0], c[r][1]);
    }
}

// ---- head: cos 4x4 -> conv1 relu -> conv2 relu -> scorer -> sigmoid ----
__global__ void k_head(const float* __restrict__ c1w, const float* __restrict__ c1b,
                       const float* __restrict__ c2w, const float* __restrict__ c2b,
                       const float* __restrict__ scw, const float* __restrict__ scb,
                       float* __restrict__ out) {
    int gw   = blockIdx.x * 8 + (threadIdx.x >> 5);   // one warp per batch b
    int lane = threadIdx.x & 31;
    if (gw >= BB) return;

    const float* rp = g_reps + (size_t)gw * (NW * HH);
    float4 rv[4];
#pragma unroll
    for (int i = 0; i < 4; ++i)
        rv[i] = *(const float4*)(rp + i * HH + lane * 4);

    const int pi[10] = {0,0,0,0,1,1,1,2,2,3};
    const int pj[10] = {0,1,2,3,1,2,3,2,3,3};
    float dots[10];
#pragma unroll
    for (int d = 0; d < 10; ++d) {
        float4 a = rv[pi[d]], b = rv[pj[d]];
        float s = a.x*b.x + a.y*b.y + a.z*b.z + a.w*b.w;
#pragma unroll
        for (int o = 16; o; o >>= 1) s += __shfl_xor_sync(0xffffffffu, s, o);
        dots[d] = s;
    }
    if (lane) return;

    float nn[4] = { rsqrtf(dots[0]), rsqrtf(dots[4]), rsqrtf(dots[7]), rsqrtf(dots[9]) };
    const int dmap[4][4] = {{0,1,2,3},{1,4,5,6},{2,5,7,8},{3,6,8,9}};
    float cm[4][4];
#pragma unroll
    for (int i = 0; i < 4; ++i)
#pragma unroll
        for (int j = 0; j < 4; ++j)
            cm[i][j] = dots[dmap[i][j]] * nn[i] * nn[j];

    float o1[4][3][3];
#pragma unroll
    for (int cc = 0; cc < 4; ++cc) {
        float w00 = c1w[cc*4+0], w01 = c1w[cc*4+1];
        float w10 = c1w[cc*4+2], w11 = c1w[cc*4+3];
        float bb = c1b[cc];
#pragma unroll
        for (int y = 0; y < 3; ++y)
#pragma unroll
            for (int x = 0; x < 3; ++x)
                o1[cc][y][x] = fmaxf(bb + w00*cm[y][x] + w01*cm[y][x+1]
                                        + w10*cm[y+1][x] + w11*cm[y+1][x+1], 0.f);
    }
    float score = scb[0];
#pragma unroll
    for (int oc = 0; oc < 8; ++oc) {
        float bb = c2b[oc];
#pragma unroll
        for (int y = 0; y < 2; ++y)
#pragma unroll
            for (int x = 0; x < 2; ++x) {
                float s = bb;
#pragma unroll
                for (int ic = 0; ic < 4; ++ic) {
                    const float* w = c2w + ((oc*4 + ic) * 4);
                    s += w[0]*o1[ic][y][x]   + w[1]*o1[ic][y][x+1]
                       + w[2]*o1[ic][y+1][x] + w[3]*o1[ic][y+1][x+1];
                }
                score += fmaxf(s, 0.f) * scw[oc*4 + y*2 + x];
            }
    }
    out[gw] = sigm_exact(score);
}

extern "C" void kernel_launch(void* const* d_in, const int* in_sizes, int n_in,
                              void* d_out, int out_size) {
    const int*   word_ids = (const int*)  d_in[0];
    const int*   lengths  = (const int*)  d_in[1];
    const float* emb      = (const float*)d_in[2];
    const float* Wih      = (const float*)d_in[3];
    const float* Whh      = (const float*)d_in[4];
    const float* bih      = (const float*)d_in[5];
    const float* bhh      = (const float*)d_in[6];
    const float* c1w      = (const float*)d_in[7];
    const float* c1b      = (const float*)d_in[8];
    const float* c2w      = (const float*)d_in[9];
    const float* c2b      = (const float*)d_in[10];
    const float* scw      = (const float*)d_in[11];
    const float* scb      = (const float*)d_in[12];
    float* out = (float*)d_out;

    k_prep<<<1, 1024>>>(lengths);
    k_scatter<<<BN_TOT/256, 256>>>(lengths);
    k_gates<<<96, G4H>>>(emb, Wih, bih, bhh, Whh);
    k_lstm<<<BN_TOT/32, 256>>>(word_ids, lengths);
    k_head<<<BB/8, 256>>>(c1w, c1b, c2w, c2b, scw, scb, out);
}

// round 7
// speedup vs baseline: 1.0447x; 1.0447x over previous
#include <cuda_runtime.h>

#define BB   8192
#define NW   4
#define LL   16
#define EE   128
#define HH   128
#define VV   64
#define BN_TOT (BB*NW)
#define G4H  512

typedef unsigned long long u64;

__device__ __align__(16) float g_G[VV * G4H];          // input gates per vocab word
__device__ __align__(16) float g_Wt[HH * G4H];         // W_hh transposed: [k][j]
__device__ __align__(16) float g_reps[(size_t)BN_TOT * HH];
__device__ int g_perm[BN_TOT];
__device__ int g_cursor[16];

__device__ __forceinline__ u64 dup2(float a) {
    u64 v; asm("mov.b64 %0, {%1, %1};" : "=l"(v) : "f"(a)); return v;
}
__device__ __forceinline__ u64 pk(float a, float b) {
    u64 v; asm("mov.b64 %0, {%1, %2};" : "=l"(v) : "f"(a), "f"(b)); return v;
}
__device__ __forceinline__ void unpk(u64 v, float& a, float& b) {
    asm("mov.b64 {%0, %1}, %2;" : "=f"(a), "=f"(b) : "l"(v));
}
__device__ __forceinline__ float tanha(float x) {
    float y; asm("tanh.approx.f32 %0, %1;" : "=f"(y) : "f"(x)); return y;
}
__device__ __forceinline__ float sigma_(float x) {        // sigmoid via tanh
    return fmaf(0.5f, tanha(0.5f * x), 0.5f);
}
__device__ __forceinline__ float sigm_exact(float x) {
    return __fdividef(1.f, 1.f + __expf(-x));
}

// ---- one-block: histogram lengths (desc bins) + exclusive scan -> g_cursor ----
__global__ void k_prep(const int* __restrict__ lengths) {
    __shared__ int bins[16][33];
    int tid = threadIdx.x, w = tid >> 5;
    for (int i = tid; i < 16 * 33; i += 1024) (&bins[0][0])[i] = 0;
    __syncthreads();
    for (int i = tid; i < BN_TOT; i += 1024)
        atomicAdd(&bins[16 - lengths[i]][w], 1);
    __syncthreads();
    if (tid < 16) {
        int s = 0;
        for (int ww = 0; ww < 32; ++ww) s += bins[tid][ww];
        bins[tid][32] = s;
    }
    __syncthreads();
    if (tid == 0) {
        int cum = 0;
        for (int b = 0; b < 16; ++b) { g_cursor[b] = cum; cum += bins[b][32]; }
    }
}

// ---- scatter rows into length-descending order ----
__global__ void k_scatter(const int* __restrict__ lengths) {
    __shared__ int cnt[16], base[16];
    int tid = threadIdx.x;
    if (tid < 16) cnt[tid] = 0;
    __syncthreads();
    int bn  = blockIdx.x * 256 + tid;
    int bin = 16 - lengths[bn];
    int rank = atomicAdd(&cnt[bin], 1);
    __syncthreads();
    if (tid < 16) base[tid] = atomicAdd(&g_cursor[tid], cnt[tid]);
    __syncthreads();
    g_perm[base[bin] + rank] = bn;
}

// ---- blocks 0..63: G[v][j] = emb[v].W_ih[j] + b_ih[j] + b_hh[j]
// ---- blocks 64..95: transpose W_hh -> g_Wt[k][j]
__global__ void k_gates(const float* __restrict__ emb, const float* __restrict__ Wih,
                        const float* __restrict__ bih, const float* __restrict__ bhh,
                        const float* __restrict__ Whh) {
    int j = threadIdx.x;
    if (blockIdx.x < 64) {
        int v = blockIdx.x;
        const float* e = emb + v * EE;
        const float* w = Wih + j * EE;
        float s = bih[j] + bhh[j];
#pragma unroll 8
        for (int k = 0; k < EE; ++k) s = fmaf(e[k], w[k], s);
        g_G[v * G4H + j] = s;
    } else {
        int kb = (blockIdx.x - 64) * 4;
#pragma unroll
        for (int kk = 0; kk < 4; ++kk)
            g_Wt[(kb + kk) * G4H + j] = Whh[j * HH + kb + kk];
    }
}

// ---- masked LSTM over length-sorted rows ----
// CTA = 32 rows, 256 threads. Warp (rh,ch): rh owns rows [8rh,8rh+8), ch a
// 64-wide hidden half; thread cols {g*128 + 64*ch + 2*lane, +1}. W fetched via
// coalesced LDG.64 from transposed g_Wt (L1-resident, warp-staggered k order).
// Only the 2 warps sharing a row group synchronize (named barrier), and each
// group runs to its own max length.
__global__ __launch_bounds__(256, 2)
void k_lstm(const int* __restrict__ word_ids, const int* __restrict__ lengths) {
    __shared__ __align__(16) float sH[32][128];
    __shared__ int sBn[32], sLen[32], sWid[32][LL];

    int tid  = threadIdx.x;
    int lane = tid & 31;
    int wrp  = tid >> 5;
    int rh   = wrp >> 1;
    int ch   = wrp & 1;
    int base = blockIdx.x * 32;
    int colh = 64 * ch + 2 * lane;
    int row0 = rh * 8;

    if (tid < 32) {
        int bn = g_perm[base + tid];
        sBn[tid] = bn; sLen[tid] = lengths[bn];
    }
    __syncthreads();
    for (int i = tid; i < 32 * LL; i += 256) {
        int r = i >> 4, t = i & 15;
        sWid[r][t] = word_ids[sBn[r] * LL + t];
    }
    for (int i = tid; i < 32 * 128; i += 256) (&sH[0][0])[i] = 0.f;
    __syncthreads();

    int tLen = 0;
#pragma unroll
    for (int r = 0; r < 8; ++r) tLen = max(tLen, sLen[row0 + r]);

    // warp-staggered k start: 16 warps/SM spread over 64 k-pair slots
    int sstart = ((wrp + ((blockIdx.x & 1) << 3)) & 15) << 2;

    float c[8][2];
#pragma unroll
    for (int r = 0; r < 8; ++r) { c[r][0] = 0.f; c[r][1] = 0.f; }

    for (int t = 0; t < tLen; ++t) {
        u64 acc[8][4];
#pragma unroll
        for (int r = 0; r < 8; ++r) {
            const u64* Gp = (const u64*)(g_G + sWid[row0 + r][t] * G4H + colh);
#pragma unroll
            for (int g = 0; g < 4; ++g) acc[r][g] = Gp[g * 64];
        }
        for (int kc = 0; kc < 64; ++kc) {
            int k = (((kc + sstart) & 63) << 1);
            float2 h2[8];
#pragma unroll
            for (int r = 0; r < 8; ++r)
                h2[r] = *(const float2*)&sH[row0 + r][k];
            u64 wA[4], wB[4];
            const float* wk = g_Wt + k * G4H + colh;
#pragma unroll
            for (int g = 0; g < 4; ++g) wA[g] = *(const u64*)(wk + g * 128);
#pragma unroll
            for (int g = 0; g < 4; ++g) wB[g] = *(const u64*)(wk + G4H + g * 128);
#pragma unroll
            for (int r = 0; r < 8; ++r) {
                u64 ha = dup2(h2[r].x);
#pragma unroll
                for (int g = 0; g < 4; ++g)
                    asm("fma.rn.f32x2 %0, %1, %2, %0;"
                        : "+l"(acc[r][g]) : "l"(ha), "l"(wA[g]));
            }
#pragma unroll
            for (int r = 0; r < 8; ++r) {
                u64 hb = dup2(h2[r].y);
#pragma unroll
                for (int g = 0; g < 4; ++g)
                    asm("fma.rn.f32x2 %0, %1, %2, %0;"
                        : "+l"(acc[r][g]) : "l"(hb), "l"(wB[g]));
            }
        }
        // pair barrier: h reads of this step complete (warps 2rh, 2rh+1)
        asm volatile("bar.sync %0, 64;" :: "r"(rh + 1) : "memory");
#pragma unroll
        for (int r = 0; r < 8; ++r) {
            int row = row0 + r;
            if (t < sLen[row]) {
                float i0, i1, f0, f1, gg0, gg1, o0, o1;
                unpk(acc[r][0], i0, i1); unpk(acc[r][1], f0, f1);
                unpk(acc[r][2], gg0, gg1); unpk(acc[r][3], o0, o1);
                float c0 = fmaf(sigma_(f0), c[r][0], sigma_(i0) * tanha(gg0));
                float c1 = fmaf(sigma_(f1), c[r][1], sigma_(i1) * tanha(gg1));
                c[r][0] = c0; c[r][1] = c1;
                *(u64*)(&sH[row][colh]) = pk(sigma_(o0) * tanha(c0),
                                             sigma_(o1) * tanha(c1));
            }
        }
        // pair barrier: h writes visible before next step's reads
        asm volatile("bar.sync %0, 64;" :: "r"(rh + 1) : "memory");
    }
#pragma unroll
    for (int r = 0; r < 8; ++r) {
        size_t bn = (size_t)sBn[row0 + r];
        *(u64*)(g_reps + bn * HH + colh) = pk(c[r][0], c[r][1]);
    }
}

// ---- head: cos 4x4 -> conv1 relu -> conv2 relu -> scorer -> sigmoid ----
__global__ void k_head(const float* __restrict__ c1w, const float* __restrict__ c1b,
                       const float* __restrict__ c2w, const float* __restrict__ c2b,
                       const float* __restrict__ scw, const float* __restrict__ scb,
                       float* __restrict__ out) {
    int gw   = blockIdx.x * 8 + (threadIdx.x >> 5);   // one warp per batch b
    int lane = threadIdx.x & 31;
    if (gw >= BB) return;

    const float* rp = g_reps + (size_t)gw * (NW * HH);
    float4 rv[4];
#pragma unroll
    for (int i = 0; i < 4; ++i)
        rv[i] = *(const float4*)(rp + i * HH + lane * 4);

    const int pi[10] = {0,0,0,0,1,1,1,2,2,3};
    const int pj[10] = {0,1,2,3,1,2,3,2,3,3};
    float dots[10];
#pragma unroll
    for (int d = 0; d < 10; ++d) {
        float4 a = rv[pi[d]], b = rv[pj[d]];
        float s = a.x*b.x + a.y*b.y + a.z*b.z + a.w*b.w;
#pragma unroll
        for (int o = 16; o; o >>= 1) s += __shfl_xor_sync(0xffffffffu, s, o);
        dots[d] = s;
    }
    if (lane) return;

    float nn[4] = { rsqrtf(dots[0]), rsqrtf(dots[4]), rsqrtf(dots[7]), rsqrtf(dots[9]) };
    const int dmap[4][4] = {{0,1,2,3},{1,4,5,6},{2,5,7,8},{3,6,8,9}};
    float cm[4][4];
#pragma unroll
    for (int i = 0; i < 4; ++i)
#pragma unroll
        for (int j = 0; j < 4; ++j)
            cm[i][j] = dots[dmap[i][j]] * nn[i] * nn[j];

    float o1[4][3][3];
#pragma unroll
    for (int cc = 0; cc < 4; ++cc) {
        float w00 = c1w[cc*4+0], w01 = c1w[cc*4+1];
        float w10 = c1w[cc*4+2], w11 = c1w[cc*4+3];
        float bb = c1b[cc];
#pragma unroll
        for (int y = 0; y < 3; ++y)
#pragma unroll
            for (int x = 0; x < 3; ++x)
                o1[cc][y][x] = fmaxf(bb + w00*cm[y][x] + w01*cm[y][x+1]
                                        + w10*cm[y+1][x] + w11*cm[y+1][x+1], 0.f);
    }
    float score = scb[0];
#pragma unroll
    for (int oc = 0; oc < 8; ++oc) {
        float bb = c2b[oc];
#pragma unroll
        for (int y = 0; y < 2; ++y)
#pragma unroll
            for (int x = 0; x < 2; ++x) {
                float s = bb;
#pragma unroll
                for (int ic = 0; ic < 4; ++ic) {
                    const float* w = c2w + ((oc*4 + ic) * 4);
                    s += w[0]*o1[ic][y][x]   + w[1]*o1[ic][y][x+1]
                       + w[2]*o1[ic][y+1][x] + w[3]*o1[ic][y+1][x+1];
                }
                score += fmaxf(s, 0.f) * scw[oc*4 + y*2 + x];
            }
    }
    out[gw] = sigm_exact(score);
}

extern "C" void kernel_launch(void* const* d_in, const int* in_sizes, int n_in,
                              void* d_out, int out_size) {
    const int*   word_ids = (const int*)  d_in[0];
    const int*   lengths  = (const int*)  d_in[1];
    const float* emb      = (const float*)d_in[2];
    const float* Wih      = (const float*)d_in[3];
    const float* Whh      = (const float*)d_in[4];
    const float* bih      = (const float*)d_in[5];
    const float* bhh      = (const float*)d_in[6];
    const float* c1w      = (const float*)d_in[7];
    const float* c1b      = (const float*)d_in[8];
    const float* c2w      = (const float*)d_in[9];
    const float* c2b      = (const float*)d_in[10];
    const float* scw      = (const float*)d_in[11];
    const float* scb      = (const float*)d_in[12];
    float* out = (float*)d_out;

    k_prep<<<1, 1024>>>(lengths);
    k_scatter<<<BN_TOT/256, 256>>>(lengths);
    k_gates<<<96, G4H>>>(emb, Wih, bih, bhh, Whh);
    k_lstm<<<BN_TOT/32, 256>>>(word_ids, lengths);
    k_head<<<BB/8, 256>>>(c1w, c1b, c2w, c2b, scw, scb, out);
}

// round 9
// speedup vs baseline: 4.0833x; 3.9084x over previous
#include <cuda_runtime.h>
#include <cuda_fp16.h>

#define BB 8192
#define NW 4
#define LL 16
#define EE 128
#define HH 128
#define VV 64
#define BN_TOT (BB*NW)
#define G4H 512

typedef unsigned int u32;

__device__ __align__(16) float g_G[VV * G4H];
__device__ __align__(16) float g_reps[(size_t)BN_TOT * HH];
__device__ int g_perm[BN_TOT];
__device__ int g_cursor[16];

// ---- dynamic smem map for k_lstm (bytes) ----
#define SM_W   0            // W_hh f16 [512][128], row stride 256B, XOR-swizzled
#define SM_G   131072       // G f16 [64][514] (stride 1028B)
#define SM_WID 196864       // u8 [128][16]
#define SM_LEN 198912       // u8 [128]
#define SM_BN  199040       // int [128]
#define SM_BYTES 199552

__device__ __forceinline__ float tanha(float x) {
    float y; asm("tanh.approx.f32 %0, %1;" : "=f"(y) : "f"(x)); return y;
}
__device__ __forceinline__ float sigma_(float x) { return fmaf(0.5f, tanha(0.5f * x), 0.5f); }
__device__ __forceinline__ float sigm_exact(float x) { return __fdividef(1.f, 1.f + __expf(-x)); }

__device__ __forceinline__ u32 s2u(const void* p) {
    u32 a; asm("{.reg .u64 t; cvta.to.shared.u64 t, %1; cvt.u32.u64 %0, t;}" : "=r"(a) : "l"(p));
    return a;
}
__device__ __forceinline__ void ldsm4(u32* r, u32 addr) {
    asm volatile("ldmatrix.sync.aligned.m8n8.x4.shared.b16 {%0,%1,%2,%3}, [%4];"
        : "=r"(r[0]), "=r"(r[1]), "=r"(r[2]), "=r"(r[3]) : "r"(addr));
}
__device__ __forceinline__ void mma16816(float* c, const u32* a, const u32* b) {
    asm volatile("mma.sync.aligned.m16n8k16.row.col.f32.f16.f16.f32 "
        "{%0,%1,%2,%3}, {%4,%5,%6,%7}, {%8,%9}, {%0,%1,%2,%3};"
        : "+f"(c[0]), "+f"(c[1]), "+f"(c[2]), "+f"(c[3])
        : "r"(a[0]), "r"(a[1]), "r"(a[2]), "r"(a[3]), "r"(b[0]), "r"(b[1]));
}
__device__ __forceinline__ u32 packh2(float a, float b) {
    __half2 h = __floats2half2_rn(a, b);
    return *(u32*)&h;
}

// ---- length histogram (desc bins) + scan ----
__global__ void k_prep(const int* __restrict__ lengths) {
    __shared__ int bins[16][33];
    int tid = threadIdx.x, w = tid >> 5;
    for (int i = tid; i < 16 * 33; i += 1024) (&bins[0][0])[i] = 0;
    __syncthreads();
    for (int i = tid; i < BN_TOT; i += 1024)
        atomicAdd(&bins[16 - lengths[i]][w], 1);
    __syncthreads();
    if (tid < 16) {
        int s = 0;
        for (int ww = 0; ww < 32; ++ww) s += bins[tid][ww];
        bins[tid][32] = s;
    }
    __syncthreads();
    if (tid == 0) {
        int cum = 0;
        for (int b = 0; b < 16; ++b) { g_cursor[b] = cum; cum += bins[b][32]; }
    }
}
__global__ void k_scatter(const int* __restrict__ lengths) {
    __shared__ int cnt[16], base[16];
    int tid = threadIdx.x;
    if (tid < 16) cnt[tid] = 0;
    __syncthreads();
    int bn = blockIdx.x * 256 + tid;
    int bin = 16 - lengths[bn];
    int rank = atomicAdd(&cnt[bin], 1);
    __syncthreads();
    if (tid < 16) base[tid] = atomicAdd(&g_cursor[tid], cnt[tid]);
    __syncthreads();
    g_perm[base[bin] + rank] = bn;
}
// ---- G[v][j] = emb[v].W_ih[j] + b_ih[j] + b_hh[j] ----
__global__ void k_gates(const float* __restrict__ emb, const float* __restrict__ Wih,
                        const float* __restrict__ bih, const float* __restrict__ bhh) {
    int v = blockIdx.x, j = threadIdx.x;
    const float* e = emb + v * EE;
    const float* w = Wih + j * EE;
    float s = bih[j] + bhh[j];
#pragma unroll 8
    for (int k = 0; k < EE; ++k) s = fmaf(e[k], w[k], s);
    g_G[v * G4H + j] = s;
}

// ---- HMMA LSTM: warp = 16 rows, h in registers as A-fragments ----
__global__ __launch_bounds__(256, 1)
void k_lstm(const int* __restrict__ wid_g, const int* __restrict__ len_g,
            const float* __restrict__ Whh) {
    extern __shared__ char sm[];
    const u32 sb = s2u(sm);
    const int tid = threadIdx.x, lane = tid & 31, w = tid >> 5;
    const int gid = lane >> 2, t4 = lane & 3;
    const int base = blockIdx.x * 128;

    // W_hh -> f16 swizzled smem
    for (int i = tid; i < 32768; i += 256) {
        int j = i >> 6, kp = i & 63;
        float2 wv = *(const float2*)(Whh + j * 128 + kp * 2);
        u32 o = (u32)(j * 256 + kp * 4);
        *(__half2*)(sm + SM_W + (o ^ ((o >> 4) & 0x70))) = __floats2half2_rn(wv.x, wv.y);
    }
    // G -> f16 smem (padded stride)
    for (int i = tid; i < VV * 256; i += 256) {
        int v = i >> 8, kp = i & 255;
        float2 gv = *(const float2*)(g_G + v * 512 + kp * 2);
        *(__half2*)(sm + SM_G + v * 1028 + kp * 4) = __floats2half2_rn(gv.x, gv.y);
    }
    if (tid < 128) {
        int bn = g_perm[base + tid];
        ((int*)(sm + SM_BN))[tid] = bn;
        ((unsigned char*)(sm + SM_LEN))[tid] = (unsigned char)len_g[bn];
    }
    __syncthreads();
    for (int i = tid; i < 128 * 16; i += 256) {
        int r = i >> 4, t = i & 15;
        ((unsigned char*)(sm + SM_WID))[i] =
            (unsigned char)wid_g[((const int*)(sm + SM_BN))[r] * 16 + t];
    }
    __syncthreads();

    const unsigned char* LEN = (const unsigned char*)(sm + SM_LEN);
    const unsigned char* WID = (const unsigned char*)(sm + SM_WID);
    const int r0 = 16 * w + gid, r1 = r0 + 8;
    const int l0 = LEN[r0], l1 = LEN[r1];
    const int tw = LEN[16 * w];            // sorted desc: first row = warp max

    // per-lane ldmatrix(B) addressing: rows j0+(lane&7)+((lane>>4)<<3), k half by bit3
    const int jl = (lane & 7) + ((lane >> 4) << 3);
    const u32 wka = (u32)(((lane >> 3) & 1) << 4);
    const u32 wmask = (u32)((lane & 7) << 4);
    const u32 wbase = sb + SM_W;

    float c[8][2][2][2];
    u32 h2[16][2], h2n[16][2];
#pragma unroll
    for (int g8 = 0; g8 < 16; ++g8) { h2[g8][0] = 0u; h2[g8][1] = 0u; }
#pragma unroll
    for (int hh = 0; hh < 8; ++hh)
#pragma unroll
        for (int s = 0; s < 2; ++s) {
            c[hh][s][0][0] = 0.f; c[hh][s][0][1] = 0.f;
            c[hh][s][1][0] = 0.f; c[hh][s][1][1] = 0.f;
        }

    for (int t = 0; t < tw; ++t) {
        int v0 = WID[r0 * 16 + t], v1 = WID[r1 * 16 + t];
        const char* gp0 = sm + SM_G + v0 * 1028 + t4 * 4;
        const char* gp1 = sm + SM_G + v1 * 1028 + t4 * 4;
        bool act0 = (t < l0), act1 = (t < l1);
#pragma unroll
        for (int hh = 0; hh < 8; ++hh) {
            float acc[4][2][4];
            // accumulators init = input gates G (f16 smem)
#pragma unroll
            for (int gt = 0; gt < 4; ++gt)
#pragma unroll
                for (int s = 0; s < 2; ++s) {
                    int cb = (gt * 128 + hh * 16 + s * 8) * 2;
                    float2 f0 = __half22float2(*(const __half2*)(gp0 + cb));
                    float2 f1 = __half22float2(*(const __half2*)(gp1 + cb));
                    acc[gt][s][0] = f0.x; acc[gt][s][1] = f0.y;
                    acc[gt][s][2] = f1.x; acc[gt][s][3] = f1.y;
                }
            // gates += h @ W^T  (A-frags straight from h2 registers)
#pragma unroll
            for (int kc = 0; kc < 8; ++kc) {
                u32 a[4] = { h2[2 * kc][0], h2[2 * kc][1], h2[2 * kc + 1][0], h2[2 * kc + 1][1] };
#pragma unroll
                for (int gt = 0; gt < 4; ++gt) {
                    u32 o = (u32)((gt * 128 + hh * 16 + jl) * 256 + kc * 32) + wka;
                    u32 b[4];
                    ldsm4(b, wbase + (o ^ wmask));
                    mma16816(acc[gt][0], a, b);
                    mma16816(acc[gt][1], a, b + 2);
                }
            }
            // epilogue: thread-local LSTM cell update for 16 hidden units
#pragma unroll
            for (int s = 0; s < 2; ++s) {
                float hn[2][2];
#pragma unroll
                for (int rs = 0; rs < 2; ++rs) {
                    bool act = rs ? act1 : act0;
#pragma unroll
                    for (int cs = 0; cs < 2; ++cs) {
                        float iv = acc[0][s][rs * 2 + cs];
                        float fv = acc[1][s][rs * 2 + cs];
                        float gv = acc[2][s][rs * 2 + cs];
                        float ov = acc[3][s][rs * 2 + cs];
                        float cp = c[hh][s][rs][cs];
                        float cn = fmaf(sigma_(fv), cp, sigma_(iv) * tanha(gv));
                        if (act) c[hh][s][rs][cs] = cn;
                        hn[rs][cs] = sigma_(ov) * tanha(cn);
                    }
                }
                int g8 = 2 * hh + s;
                u32 p0 = packh2(hn[0][0], hn[0][1]);
                u32 p1 = packh2(hn[1][0], hn[1][1]);
                h2n[g8][0] = act0 ? p0 : h2[g8][0];
                h2n[g8][1] = act1 ? p1 : h2[g8][1];
            }
        }
#pragma unroll
        for (int g8 = 0; g8 < 16; ++g8) { h2[g8][0] = h2n[g8][0]; h2[g8][1] = h2n[g8][1]; }
    }

    // reps = final cell state
    const int* BN = (const int*)(sm + SM_BN);
    float* d0 = g_reps + (size_t)BN[r0] * HH;
    float* d1 = g_reps + (size_t)BN[r1] * HH;
#pragma unroll
    for (int hh = 0; hh < 8; ++hh)
#pragma unroll
        for (int s = 0; s < 2; ++s) {
            int col = hh * 16 + s * 8 + t4 * 2;
            *(float2*)(d0 + col) = make_float2(c[hh][s][0][0], c[hh][s][0][1]);
            *(float2*)(d1 + col) = make_float2(c[hh][s][1][0], c[hh][s][1][1]);
        }
}

// ---- head: cos 4x4 -> conv1 relu -> conv2 relu -> scorer -> sigmoid ----
__global__ void k_head(const float* __restrict__ c1w, const float* __restrict__ c1b,
                       const float* __restrict__ c2w, const float* __restrict__ c2b,
                       const float* __restrict__ scw, const float* __restrict__ scb,
                       float* __restrict__ out) {
    int gw = blockIdx.x * 8 + (threadIdx.x >> 5);
    int lane = threadIdx.x & 31;
    if (gw >= BB) return;
    const float* rp = g_reps + (size_t)gw * (NW * HH);
    float4 rv[4];
#pragma unroll
    for (int i = 0; i < 4; ++i) rv[i] = *(const float4*)(rp + i * HH + lane * 4);
    const int pi[10] = {0,0,0,0,1,1,1,2,2,3};
    const int pj[10] = {0,1,2,3,1,2,3,2,3,3};
    float dots[10];
#pragma unroll
    for (int d = 0; d < 10; ++d) {
        float4 a = rv[pi[d]], b = rv[pj[d]];
        float s = a.x*b.x + a.y*b.y + a.z*b.z + a.w*b.w;
#pragma unroll
        for (int o = 16; o; o >>= 1) s += __shfl_xor_sync(0xffffffffu, s, o);
        dots[d] = s;
    }
    if (lane) return;
    float nn[4] = { rsqrtf(dots[0]), rsqrtf(dots[4]), rsqrtf(dots[7]), rsqrtf(dots[9]) };
    const int dmap[4][4] = {{0,1,2,3},{1,4,5,6},{2,5,7,8},{3,6,8,9}};
    float cm[4][4];
#pragma unroll
    for (int i = 0; i < 4; ++i)
#pragma unroll
        for (int j = 0; j < 4; ++j)
            cm[i][j] = dots[dmap[i][j]] * nn[i] * nn[j];
    float o1[4][3][3];
#pragma unroll
    for (int cc = 0; cc < 4; ++cc) {
        float w00 = c1w[cc*4+0], w01 = c1w[cc*4+1], w10 = c1w[cc*4+2], w11 = c1w[cc*4+3];
        float bb = c1b[cc];
#pragma unroll
        for (int y = 0; y < 3; ++y)
#pragma unroll
            for (int x = 0; x < 3; ++x)
                o1[cc][y][x] = fmaxf(bb + w00*cm[y][x] + w01*cm[y][x+1]
                                        + w10*cm[y+1][x] + w11*cm[y+1][x+1], 0.f);
    }
    float score = scb[0];
#pragma unroll
    for (int oc = 0; oc < 8; ++oc) {
        float bb = c2b[oc];
#pragma unroll
        for (int y = 0; y < 2; ++y)
#pragma unroll
            for (int x = 0; x < 2; ++x) {
                float s = bb;
#pragma unroll
                for (int ic = 0; ic < 4; ++ic) {
                    const float* ww = c2w + ((oc*4 + ic) * 4);
                    s += ww[0]*o1[ic][y][x]   + ww[1]*o1[ic][y][x+1]
                       + ww[2]*o1[ic][y+1][x] + ww[3]*o1[ic][y+1][x+1];
                }
                score += fmaxf(s, 0.f) * scw[oc*4 + y*2 + x];
            }
    }
    out[gw] = sigm_exact(score);
}

extern "C" void kernel_launch(void* const* d_in, const int* in_sizes, int n_in,
                              void* d_out, int out_size) {
    const int*   word_ids = (const int*)  d_in[0];
    const int*   lengths  = (const int*)  d_in[1];
    const float* emb      = (const float*)d_in[2];
    const float* Wih      = (const float*)d_in[3];
    const float* Whh      = (const float*)d_in[4];
    const float* bih      = (const float*)d_in[5];
    const float* bhh      = (const float*)d_in[6];
    const float* c1w      = (const float*)d_in[7];
    const float* c1b      = (const float*)d_in[8];
    const float* c2w      = (const float*)d_in[9];
    const float* c2b      = (const float*)d_in[10];
    const float* scw      = (const float*)d_in[11];
    const float* scb      = (const float*)d_in[12];
    float* out = (float*)d_out;

    static int attr_done = 0;
    if (!attr_done) {
        cudaFuncSetAttribute(k_lstm, cudaFuncAttributeMaxDynamicSharedMemorySize, SM_BYTES);
        attr_done = 1;
    }
    k_prep<<<1, 1024>>>(lengths);
    k_scatter<<<BN_TOT/256, 256>>>(lengths);
    k_gates<<<VV, G4H>>>(emb, Wih, bih, bhh);
    k_lstm<<<BN_TOT/128, 256, SM_BYTES>>>(word_ids, lengths, Whh);
    k_head<<<BB/8, 256>>>(c1w, c1b, c2w, c2b, scw, scb, out);
}